// round 3
// baseline (speedup 1.0000x reference)
#include <cuda_runtime.h>
#include <cuda_fp16.h>

#define NNODES 150000
#define MAXE   2000000
#define EMB4   32          // 128 floats = 32 float4 per row
#define EMBH   32          // 128 halfs  = 32 uint2  per row
#define MAXB   16384
#define MAXROWS (2*MAXB)

// ---------------- static device scratch -------------------------------------
__device__ uint2  g_f0[NNODES * EMBH];   // feats as fp16 (layer 0 gather source)
__device__ uint2  g_hf1[NNODES * EMBH];  // layer 1, fp16
__device__ uint2  g_hf2[NNODES * EMBH];  // layer 2, fp16
__device__ float4 g_h3[NNODES * EMB4];   // layer 3, fp32, only needed rows written
__device__ int    g_cnt[NNODES];
__device__ int    g_rowptr[NNODES + 1];
__device__ int    g_cursor[NNODES];
__device__ int2   g_edge[MAXE];          // CSR {col, val-bits}
__device__ unsigned char g_need[NNODES];
__device__ int    g_rows[MAXROWS];
__device__ int    g_nrows;

// ---------------- helpers ----------------------------------------------------

__device__ __forceinline__ uint2 f4_to_h8(float4 a) {
    __half2 lo = __floats2half2_rn(a.x, a.y);
    __half2 hi = __floats2half2_rn(a.z, a.w);
    uint2 o;
    o.x = *reinterpret_cast<unsigned*>(&lo);
    o.y = *reinterpret_cast<unsigned*>(&hi);
    return o;
}

__device__ __forceinline__ void fma_h8(float4& acc, float v, uint2 h) {
    float2 lo = __half22float2(*reinterpret_cast<__half2*>(&h.x));
    float2 hi = __half22float2(*reinterpret_cast<__half2*>(&h.y));
    acc.x = fmaf(v, lo.x, acc.x);
    acc.y = fmaf(v, lo.y, acc.y);
    acc.z = fmaf(v, hi.x, acc.z);
    acc.w = fmaf(v, hi.y, acc.w);
}

// ---------------- CSR build --------------------------------------------------

__global__ void k_zero(int n) {
    int i = blockIdx.x * blockDim.x + threadIdx.x;
    if (i < n) { g_cnt[i] = 0; g_need[i] = 0; }
    if (i == 0) g_nrows = 0;
}

__global__ void k_hist(const int* __restrict__ row, int e) {
    int i = blockIdx.x * blockDim.x + threadIdx.x;
    if (i < e) atomicAdd(&g_cnt[row[i]], 1);
}

// single-block fused exclusive scan over g_cnt -> g_rowptr, g_cursor
__global__ void k_scan(int n) {
    __shared__ int sh[1024];
    int chunk = (n + 1023) / 1024;
    int s = threadIdx.x * chunk;
    int e = min(s + chunk, n);
    int sum = 0;
    for (int i = s; i < e; i++) sum += g_cnt[i];
    sh[threadIdx.x] = sum;
    __syncthreads();
    for (int off = 1; off < 1024; off <<= 1) {
        int t = (threadIdx.x >= off) ? sh[threadIdx.x - off] : 0;
        __syncthreads();
        sh[threadIdx.x] += t;
        __syncthreads();
    }
    int run = sh[threadIdx.x] - sum;   // exclusive prefix
    for (int i = s; i < e; i++) {
        int c = g_cnt[i];
        g_rowptr[i] = run;
        g_cursor[i] = run;
        run += c;
    }
    if (threadIdx.x == 1023) g_rowptr[n] = run;
}

__global__ void k_fill(const int* __restrict__ row, const int* __restrict__ col,
                       const float* __restrict__ val, int e) {
    int i = blockIdx.x * blockDim.x + threadIdx.x;
    if (i < e) {
        int r = row[i];
        int p = atomicAdd(&g_cursor[r], 1);
        g_edge[p] = make_int2(col[i], __float_as_int(val[i]));
    }
}

// feats -> fp16 copy (one float4 per thread)
__global__ void k_tofp16(const float4* __restrict__ uE, const float4* __restrict__ iE,
                         int userNum, int n) {
    int i = blockIdx.x * blockDim.x + threadIdx.x;
    int total = n * EMB4;
    if (i < total) {
        int node = i >> 5;
        float4 a = (node < userNum) ? uE[i] : iE[i - userNum * EMB4];
        g_f0[i] = f4_to_h8(a);
    }
}

// ---------------- SpMM (warp per row, fp16 gather / fp32 accum) --------------

__global__ void k_spmm1(int n) {
    int w    = (blockIdx.x * blockDim.x + threadIdx.x) >> 5;
    int lane = threadIdx.x & 31;
    if (w >= n) return;
    int s = g_rowptr[w], e = g_rowptr[w + 1];
    float4 acc = make_float4(0.f, 0.f, 0.f, 0.f);
    for (int base = s; base < e; base += 32) {
        int idx = base + lane;
        int2 ed = (idx < e) ? g_edge[idx] : make_int2(0, 0);
        int m = min(32, e - base);
        #pragma unroll 4
        for (int j = 0; j < m; j++) {
            int   cj = __shfl_sync(0xffffffffu, ed.x, j);
            float vj = __shfl_sync(0xffffffffu, __int_as_float(ed.y), j);
            fma_h8(acc, vj, g_f0[(size_t)cj * EMBH + lane]);
        }
    }
    g_hf1[w * EMBH + lane] = f4_to_h8(acc);
}

__global__ void k_spmm2(int n) {
    int w    = (blockIdx.x * blockDim.x + threadIdx.x) >> 5;
    int lane = threadIdx.x & 31;
    if (w >= n) return;
    int s = g_rowptr[w], e = g_rowptr[w + 1];
    float4 acc = make_float4(0.f, 0.f, 0.f, 0.f);
    for (int base = s; base < e; base += 32) {
        int idx = base + lane;
        int2 ed = (idx < e) ? g_edge[idx] : make_int2(0, 0);
        int m = min(32, e - base);
        #pragma unroll 4
        for (int j = 0; j < m; j++) {
            int   cj = __shfl_sync(0xffffffffu, ed.x, j);
            float vj = __shfl_sync(0xffffffffu, __int_as_float(ed.y), j);
            fma_h8(acc, vj, g_hf1[(size_t)cj * EMBH + lane]);
        }
    }
    g_hf2[w * EMBH + lane] = f4_to_h8(acc);
}

// layer 3 restricted to compacted sampled rows; fp32 output
__global__ void k_spmm3() {
    int w    = (blockIdx.x * blockDim.x + threadIdx.x) >> 5;
    int lane = threadIdx.x & 31;
    if (w >= g_nrows) return;
    int r = g_rows[w];
    int s = g_rowptr[r], e = g_rowptr[r + 1];
    float4 acc = make_float4(0.f, 0.f, 0.f, 0.f);
    for (int base = s; base < e; base += 32) {
        int idx = base + lane;
        int2 ed = (idx < e) ? g_edge[idx] : make_int2(0, 0);
        int m = min(32, e - base);
        #pragma unroll 4
        for (int j = 0; j < m; j++) {
            int   cj = __shfl_sync(0xffffffffu, ed.x, j);
            float vj = __shfl_sync(0xffffffffu, __int_as_float(ed.y), j);
            fma_h8(acc, vj, g_hf2[(size_t)cj * EMBH + lane]);
        }
    }
    g_h3[r * EMB4 + lane] = acc;
}

// ---------------- needed-row marking / compaction ----------------------------

__global__ void k_mark(const int* __restrict__ uIdx, const int* __restrict__ vIdx,
                       int userNum, int B) {
    int i = blockIdx.x * blockDim.x + threadIdx.x;
    if (i < B) {
        g_need[uIdx[i]] = 1;
        g_need[vIdx[i] + userNum] = 1;
    }
}

__global__ void k_compact(int n) {
    int i = blockIdx.x * blockDim.x + threadIdx.x;
    int lane = threadIdx.x & 31;
    int flag = (i < n) ? (int)g_need[i] : 0;
    unsigned m = __ballot_sync(0xffffffffu, flag);
    int cnt = __popc(m);
    if (cnt == 0) return;
    int base = 0;
    if (lane == 0) base = atomicAdd(&g_nrows, cnt);
    base = __shfl_sync(0xffffffffu, base, 0);
    if (flag) g_rows[base + __popc(m & ((1u << lane) - 1u))] = i;
}

// ---------------- final dot ---------------------------------------------------

__global__ void k_dot(const float4* __restrict__ uE, const float4* __restrict__ iE,
                      const int* __restrict__ uIdx, const int* __restrict__ vIdx,
                      int userNum, int B, float* __restrict__ out) {
    int w    = (blockIdx.x * blockDim.x + threadIdx.x) >> 5;
    int lane = threadIdx.x & 31;
    if (w >= B) return;

    int u  = uIdx[w];
    int vi = vIdx[w];
    int v  = vi + userNum;
    size_t uh = (size_t)u * EMBH + lane;
    size_t vh = (size_t)v * EMBH + lane;

    float4 su = uE[(size_t)u * EMB4 + lane];    // layer 0, fp32
    float4 sv = iE[(size_t)vi * EMB4 + lane];
    fma_h8(su, 1.f, g_hf1[uh]);
    fma_h8(su, 1.f, g_hf2[uh]);
    fma_h8(sv, 1.f, g_hf1[vh]);
    fma_h8(sv, 1.f, g_hf2[vh]);
    float4 a3 = g_h3[(size_t)u * EMB4 + lane];  // layer 3, fp32
    float4 b3 = g_h3[(size_t)v * EMB4 + lane];
    su.x += a3.x; su.y += a3.y; su.z += a3.z; su.w += a3.w;
    sv.x += b3.x; sv.y += b3.y; sv.z += b3.z; sv.w += b3.w;

    float d = su.x * sv.x + su.y * sv.y + su.z * sv.z + su.w * sv.w;
    #pragma unroll
    for (int off = 16; off > 0; off >>= 1)
        d += __shfl_xor_sync(0xffffffffu, d, off);

    if (lane == 0) out[w] = d * 0.0625f;   // (1/4)*(1/4)
}

// ---------------- launch ------------------------------------------------------

extern "C" void kernel_launch(void* const* d_in, const int* in_sizes, int n_in,
                              void* d_out, int out_size) {
    const float4* uE   = (const float4*)d_in[0];
    const float4* iE   = (const float4*)d_in[1];
    const float*  Lval = (const float*)d_in[2];
    const int*    Lrow = (const int*)d_in[3];
    const int*    Lcol = (const int*)d_in[4];
    const int*    uIdx = (const int*)d_in[5];
    const int*    vIdx = (const int*)d_in[6];
    float*        out  = (float*)d_out;

    int userNum = in_sizes[0] / 128;
    int itemNum = in_sizes[1] / 128;
    int n = userNum + itemNum;
    if (n > NNODES) n = NNODES;
    int e = in_sizes[2];
    if (e > MAXE) e = MAXE;
    int B = in_sizes[5];
    if (B > MAXB) B = MAXB;

    // launch order chosen so ncu -s 5 captures k_spmm1 (launch index 5)
    k_zero  <<<(n + 255) / 256, 256>>>(n);                       // 0
    k_hist  <<<(e + 255) / 256, 256>>>(Lrow, e);                 // 1
    k_scan  <<<1, 1024>>>(n);                                    // 2
    k_fill  <<<(e + 255) / 256, 256>>>(Lrow, Lcol, Lval, e);     // 3
    k_tofp16<<<(n * EMB4 + 255) / 256, 256>>>(uE, iE, userNum, n); // 4

    int spmm_blocks = (n + 7) / 8;
    k_spmm1<<<spmm_blocks, 256>>>(n);                            // 5  <- profiled
    k_spmm2<<<spmm_blocks, 256>>>(n);                            // 6

    k_mark   <<<(B + 255) / 256, 256>>>(uIdx, vIdx, userNum, B); // 7
    k_compact<<<(n + 255) / 256, 256>>>(n);                      // 8
    k_spmm3  <<<(MAXROWS + 7) / 8, 256>>>();                     // 9

    k_dot<<<(B + 7) / 8, 256>>>(uE, iE, uIdx, vIdx, userNum, B, out); // 10
}